// round 7
// baseline (speedup 1.0000x reference)
#include <cuda_runtime.h>
#include <cstdint>

#define NN 100000
#define EE 800000
#define DD 300
#define ETOT (EE + NN)

// tf32 GEMM config: K padded to 320, chunks of 32
#define KPAD 320
#define KC   32
#define NCH  (KPAD / KC)    // 10
#define STRF 36             // smem row stride in floats (144 B)

// ---------------- scratch (static device memory; no allocation) ----------------
__device__ int   g_is64;
__device__ int   g_deg[NN];
__device__ int   g_cnt[NN];
__device__ int   g_cursor[NN];
__device__ int   g_rowptr[NN + 1];
__device__ float g_dis[NN];
__device__ int   g_srcv[ETOT];
__device__ float g_wv[ETOT];
__device__ __align__(16) float g_bufA[(size_t)NN * DD];   // GEMM output
__device__ __align__(16) float g_bufB[(size_t)NN * DD];   // layer-1 agg output

// ---------------- PTX helpers (baseline sm_80-era ISA only) ----------------
__device__ __forceinline__ uint32_t smem_u32(const void* p) {
    uint32_t a;
    asm("{ .reg .u64 t; cvta.to.shared.u64 t, %1; cvt.u32.u64 %0, t; }" : "=r"(a) : "l"(p));
    return a;
}
__device__ __forceinline__ void cp16(uint32_t saddr, const void* g, uint32_t sz) {
    asm volatile("cp.async.cg.shared.global [%0], [%1], 16, %2;"
                 :: "r"(saddr), "l"(g), "r"(sz) : "memory");
}
#define CP_COMMIT() asm volatile("cp.async.commit_group;" ::: "memory")
#define CP_WAIT(n)  asm volatile("cp.async.wait_group %0;" :: "n"(n) : "memory")

__device__ __forceinline__ void ldsm_x4(uint32_t& r0, uint32_t& r1, uint32_t& r2,
                                        uint32_t& r3, uint32_t a) {
    asm volatile("ldmatrix.sync.aligned.m8n8.x4.shared.b16 {%0,%1,%2,%3}, [%4];"
                 : "=r"(r0), "=r"(r1), "=r"(r2), "=r"(r3) : "r"(a));
}
__device__ __forceinline__ void ldsm_x2(uint32_t& r0, uint32_t& r1, uint32_t a) {
    asm volatile("ldmatrix.sync.aligned.m8n8.x2.shared.b16 {%0,%1}, [%2];"
                 : "=r"(r0), "=r"(r1) : "r"(a));
}
__device__ __forceinline__ void cvt_tf32(uint32_t& x) {
    asm("cvt.rna.tf32.f32 %0, %0;" : "+r"(x));
}
__device__ __forceinline__ void mma_tf32(float* c, const uint32_t* a, const uint32_t* b) {
    asm volatile("mma.sync.aligned.m16n8k8.row.col.f32.tf32.tf32.f32 "
                 "{%0,%1,%2,%3}, {%4,%5,%6,%7}, {%8,%9}, {%0,%1,%2,%3};"
                 : "+f"(c[0]), "+f"(c[1]), "+f"(c[2]), "+f"(c[3])
                 : "r"(a[0]), "r"(a[1]), "r"(a[2]), "r"(a[3]), "r"(b[0]), "r"(b[1]));
}

// ---------------- edge dtype detection + init (merged) ----------------
__global__ void k_detect_init(const unsigned int* __restrict__ ei32) {
    const int gtid = blockIdx.x * blockDim.x + threadIdx.x;
    if (blockIdx.x == 0) {
        // int64 values < 2^31 -> zero high words at odd u32 positions
        unsigned v = ei32[2 * threadIdx.x + 1];
        if (threadIdx.x == 0) g_is64 = 1;
        __syncthreads();
        if (v) g_is64 = 0;
    }
    for (int i = gtid; i < NN; i += gridDim.x * blockDim.x) {
        g_deg[i] = 1;   // self loop
        g_cnt[i] = 1;
    }
}

__device__ __forceinline__ int load_edge(const void* __restrict__ ei, int idx) {
    if (g_is64) return (int)((const long long*)ei)[idx];
    return ((const int*)ei)[idx];
}

// ---------------- setup kernels ----------------
__global__ void k_count(const void* __restrict__ ei) {
    for (int e = blockIdx.x * blockDim.x + threadIdx.x; e < EE;
         e += gridDim.x * blockDim.x) {
        int s = load_edge(ei, e);
        int d = load_edge(ei, EE + e);
        if ((unsigned)s < NN && (unsigned)d < NN) {
            atomicAdd(&g_deg[s], 1);
            atomicAdd(&g_cnt[d], 1);
        }
    }
}

// scan of g_cnt -> rowptr/cursor, plus g_dis = deg^-0.5 (merged)
__global__ __launch_bounds__(1024) void k_scan_dis() {
    __shared__ int ssum[1024];
    const int t  = threadIdx.x;
    const int CH = (NN + 1023) / 1024;
    const int base = t * CH;

    int s = 0;
    for (int i = 0; i < CH; i++) {
        int idx = base + i;
        if (idx < NN) {
            s += g_cnt[idx];
            g_dis[idx] = rsqrtf((float)g_deg[idx]);
        }
    }
    ssum[t] = s;
    __syncthreads();
    for (int off = 1; off < 1024; off <<= 1) {
        int v = (t >= off) ? ssum[t - off] : 0;
        __syncthreads();
        ssum[t] += v;
        __syncthreads();
    }
    int run = (t == 0) ? 0 : ssum[t - 1];
    for (int i = 0; i < CH; i++) {
        int idx = base + i;
        if (idx < NN) {
            g_rowptr[idx] = run;
            g_cursor[idx] = run;
            run += g_cnt[idx];
        }
    }
    if (t == 1023) g_rowptr[NN] = ssum[1023];
}

__global__ void k_scatter(const void* __restrict__ ei) {
    for (int e = blockIdx.x * blockDim.x + threadIdx.x; e < ETOT;
         e += gridDim.x * blockDim.x) {
        int s, d;
        if (e < EE) {
            s = load_edge(ei, e);
            d = load_edge(ei, EE + e);
            if ((unsigned)s >= NN || (unsigned)d >= NN) continue;
        } else {
            s = d = e - EE;
        }
        int pos = atomicAdd(&g_cursor[d], 1);
        if ((unsigned)pos < ETOT) {
            g_srcv[pos] = s;
            g_wv[pos]   = g_dis[s] * g_dis[d];
        }
    }
}

// ---------------- tf32 mma GEMM ----------------
// g_bufA[M,300] = A[M,300] @ W[300,300]^T + bias (fp32 in/out, tf32 compute)
// CTA 128x160, 8 warps (2 M x 4 N), warp tile 64x40; K in 10 chunks of 32,
// double-buffered smem via cp.async. src_flag: 0 -> Aext (x), 1 -> g_bufB.
#define SA_BYTES (128 * STRF * 4)     // 18432
#define SB_BYTES (160 * STRF * 4)     // 23040
#define SMEM_MMA (2 * SA_BYTES + 2 * SB_BYTES)   // 82944

__global__ void __launch_bounds__(256) k_gemm_tf32(const float* __restrict__ Aext,
                                                   const float* __restrict__ W,
                                                   const float* __restrict__ bias,
                                                   int src_flag) {
    extern __shared__ char smem[];
    const float* __restrict__ A = src_flag ? g_bufB : Aext;
    const uint32_t sb   = smem_u32(smem);
    const int tid  = threadIdx.x;
    const int wid  = tid >> 5;
    const int lane = tid & 31;
    const int wm   = wid & 1;
    const int wn   = wid >> 1;
    const int bm   = blockIdx.x * 128;
    const int bn   = blockIdx.y * 160;

    const uint32_t sA[2] = { sb,                sb + SA_BYTES };
    const uint32_t sB[2] = { sb + 2 * SA_BYTES, sb + 2 * SA_BYTES + SB_BYTES };

    float acc[4][5][4];
#pragma unroll
    for (int i = 0; i < 4; i++)
#pragma unroll
        for (int j = 0; j < 5; j++)
#pragma unroll
            for (int q = 0; q < 4; q++) acc[i][j][q] = 0.f;

    auto issue = [&](int c, int b) {
        const int k0 = c * KC;
#pragma unroll
        for (int t = 0; t < 4; t++) {
            int u   = tid + 256 * t;
            int row = u >> 3;
            int kc  = (u & 7) * 4;
            int gr  = bm + row;
            int gk  = k0 + kc;
            uint32_t sz = (gr < NN && gk < DD) ? 16u : 0u;
            if (gr >= NN) gr = NN - 1;
            if (gk >= DD) gk = 0;
            cp16(sA[b] + (row * STRF + kc) * 4, A + (size_t)gr * DD + gk, sz);
        }
#pragma unroll
        for (int t = 0; t < 5; t++) {
            int u   = tid + 256 * t;
            int row = u >> 3;
            int kc  = (u & 7) * 4;
            int gr  = bn + row;
            int gk  = k0 + kc;
            uint32_t sz = (gr < DD && gk < DD) ? 16u : 0u;
            if (gr >= DD) gr = 0;
            if (gk >= DD) gk = 0;
            cp16(sB[b] + (row * STRF + kc) * 4, W + (size_t)gr * DD + gk, sz);
        }
        CP_COMMIT();
    };

    issue(0, 0);
    issue(1, 1);

    for (int c = 0; c < NCH; c++) {
        if (c < NCH - 1) CP_WAIT(1); else CP_WAIT(0);
        __syncthreads();

        const int b = c & 1;
        const uint32_t a_base = sA[b];
        const uint32_t b_base = sB[b];

#pragma unroll
        for (int s = 0; s < 4; s++) {
            const int kb = s * 8;
            uint32_t af[4][4];
#pragma unroll
            for (int i = 0; i < 4; i++) {
                uint32_t addr = a_base +
                    ((wm * 64 + i * 16 + (lane & 15)) * STRF + kb + (lane >> 4) * 4) * 4;
                ldsm_x4(af[i][0], af[i][1], af[i][2], af[i][3], addr);
                cvt_tf32(af[i][0]); cvt_tf32(af[i][1]);
                cvt_tf32(af[i][2]); cvt_tf32(af[i][3]);
            }
            uint32_t bf[5][2];
#pragma unroll
            for (int j = 0; j < 5; j++) {
                uint32_t addr = b_base +
                    ((wn * 40 + j * 8 + (lane & 7)) * STRF + kb + ((lane >> 3) & 1) * 4) * 4;
                ldsm_x2(bf[j][0], bf[j][1], addr);
                cvt_tf32(bf[j][0]); cvt_tf32(bf[j][1]);
            }
#pragma unroll
            for (int i = 0; i < 4; i++)
#pragma unroll
                for (int j = 0; j < 5; j++)
                    mma_tf32(acc[i][j], af[i], bf[j]);
        }

        __syncthreads();
        if (c + 2 < NCH) issue(c + 2, b);
    }

    const int mrow = lane >> 2;
    const int ncol = 2 * (lane & 3);
#pragma unroll
    for (int i = 0; i < 4; i++) {
#pragma unroll
        for (int j = 0; j < 5; j++) {
            int gc = bn + wn * 40 + j * 8 + ncol;
            if (gc >= DD) continue;
            float bx = __ldg(bias + gc);
            float by = __ldg(bias + gc + 1);
            int gr0 = bm + wm * 64 + i * 16 + mrow;
            if (gr0 < NN) {
                float2 v = make_float2(acc[i][j][0] + bx, acc[i][j][1] + by);
                *(float2*)(g_bufA + (size_t)gr0 * DD + gc) = v;
            }
            int gr1 = gr0 + 8;
            if (gr1 < NN) {
                float2 v = make_float2(acc[i][j][2] + bx, acc[i][j][3] + by);
                *(float2*)(g_bufA + (size_t)gr1 * DD + gc) = v;
            }
        }
    }
}

// ---------------- aggregation: warp per node, float4, 2-edge unroll ----------------
// Row = 75 float4; lane covers float4 cols {lane, lane+32, lane+64(<75)}.
#define AGG_WPB 8   // warps per block

__device__ __forceinline__ void fma4(float4& a, float w, const float4& v) {
    a.x += w * v.x; a.y += w * v.y; a.z += w * v.z; a.w += w * v.w;
}

__global__ __launch_bounds__(32 * AGG_WPB) void k_aggregate(float* __restrict__ Oext,
                                                            int dst_flag) {
    const int node = blockIdx.x * AGG_WPB + (threadIdx.x >> 5);
    if (node >= NN) return;
    const int lane = threadIdx.x & 31;
    const bool has2 = lane < 75 - 64;   // 11 lanes

    const int beg = g_rowptr[node];
    const int end = g_rowptr[node + 1];

    float4 a0 = make_float4(0.f, 0.f, 0.f, 0.f);
    float4 a1 = a0, a2 = a0;

    int e = beg;
    for (; e + 2 <= end; e += 2) {
        const int   s0 = g_srcv[e],     s1 = g_srcv[e + 1];
        const float w0 = g_wv[e],       w1 = g_wv[e + 1];
        const float4* p0 = (const float4*)(g_bufA + (size_t)s0 * DD);
        const float4* p1 = (const float4*)(g_bufA + (size_t)s1 * DD);
        float4 x0 = p0[lane],      y0 = p1[lane];
        float4 x1 = p0[lane + 32], y1 = p1[lane + 32];
        float4 x2, y2;
        if (has2) { x2 = p0[lane + 64]; y2 = p1[lane + 64]; }
        fma4(a0, w0, x0); fma4(a1, w0, x1);
        fma4(a0, w1, y0); fma4(a1, w1, y1);
        if (has2) { fma4(a2, w0, x2); fma4(a2, w1, y2); }
    }
    if (e < end) {
        const int   s0 = g_srcv[e];
        const float w0 = g_wv[e];
        const float4* p0 = (const float4*)(g_bufA + (size_t)s0 * DD);
        fma4(a0, w0, p0[lane]);
        fma4(a1, w0, p0[lane + 32]);
        if (has2) fma4(a2, w0, p0[lane + 64]);
    }

    float4* op;
    if (dst_flag) {
        op = (float4*)(Oext + (size_t)node * DD);
    } else {
        a0.x = fmaxf(a0.x, 0.f); a0.y = fmaxf(a0.y, 0.f);
        a0.z = fmaxf(a0.z, 0.f); a0.w = fmaxf(a0.w, 0.f);
        a1.x = fmaxf(a1.x, 0.f); a1.y = fmaxf(a1.y, 0.f);
        a1.z = fmaxf(a1.z, 0.f); a1.w = fmaxf(a1.w, 0.f);
        a2.x = fmaxf(a2.x, 0.f); a2.y = fmaxf(a2.y, 0.f);
        a2.z = fmaxf(a2.z, 0.f); a2.w = fmaxf(a2.w, 0.f);
        op = (float4*)(g_bufB + (size_t)node * DD);
    }
    op[lane]      = a0;
    op[lane + 32] = a1;
    if (has2) op[lane + 64] = a2;
}

// ---------------- launch ----------------
extern "C" void kernel_launch(void* const* d_in, const int* in_sizes, int n_in,
                              void* d_out, int out_size) {
    const float* x   = (const float*)d_in[0];
    const void*  ei  = d_in[1];
    const float* W1  = (const float*)d_in[2];
    const float* b1  = (const float*)d_in[3];
    const float* W2  = (const float*)d_in[4];
    const float* b2  = (const float*)d_in[5];
    float*       out = (float*)d_out;

    static int smem_set = 0;
    if (!smem_set) {
        cudaFuncSetAttribute(k_gemm_tf32, cudaFuncAttributeMaxDynamicSharedMemorySize,
                             SMEM_MMA);
        smem_set = 1;
    }

    // graph setup (4 launches, deterministic each call)
    k_detect_init<<<392, 256>>>((const unsigned int*)ei);
    k_count<<<1024, 256>>>(ei);
    k_scan_dis<<<1, 1024>>>();
    k_scatter<<<1024, 256>>>(ei);

    dim3 ggrid((NN + 127) / 128, 2);                 // 782 x 2
    const int agrid = (NN + AGG_WPB - 1) / AGG_WPB;  // 12500

    // layer 1: bufA = x @ W1^T + b1 ; bufB = relu(agg(bufA))
    k_gemm_tf32<<<ggrid, 256, SMEM_MMA>>>(x, W1, b1, 0);
    k_aggregate<<<agrid, 32 * AGG_WPB>>>(out, 0);

    // layer 2: bufA = bufB @ W2^T + b2 ; out = agg(bufA)
    k_gemm_tf32<<<ggrid, 256, SMEM_MMA>>>(nullptr, W2, b2, 1);
    k_aggregate<<<agrid, 32 * AGG_WPB>>>(out, 1);
}

// round 8
// speedup vs baseline: 1.0946x; 1.0946x over previous
#include <cuda_runtime.h>
#include <cuda_fp16.h>
#include <cstdint>

#define NN 100000
#define EE 800000
#define DD 300
#define ETOT (EE + NN)

// tf32 GEMM config: K padded to 320, chunks of 32
#define KPAD 320
#define KC   32
#define NCH  (KPAD / KC)    // 10
#define STRF 36             // smem row stride in floats (144 B)
#define HPAD 304            // fp16 feature row length (608 B, 38 x 16B chunks)

// ---------------- scratch (static device memory; no allocation) ----------------
__device__ int   g_is64;
__device__ int   g_deg[NN];
__device__ int   g_cnt[NN];
__device__ int   g_cursor[NN];
__device__ int   g_rowptr[NN + 1];
__device__ float g_dis[NN];
__device__ int   g_srcv[ETOT];
__device__ float g_wv[ETOT];
__device__ __align__(16) __half g_bufH[(size_t)NN * HPAD];  // GEMM out (fp16, 60.8MB)
__device__ __align__(16) float  g_bufB[(size_t)NN * DD];    // layer-1 agg out (fp32)

// ---------------- PTX helpers (baseline sm_80-era ISA only) ----------------
__device__ __forceinline__ uint32_t smem_u32(const void* p) {
    uint32_t a;
    asm("{ .reg .u64 t; cvta.to.shared.u64 t, %1; cvt.u32.u64 %0, t; }" : "=r"(a) : "l"(p));
    return a;
}
__device__ __forceinline__ void cp16(uint32_t saddr, const void* g, uint32_t sz) {
    asm volatile("cp.async.cg.shared.global [%0], [%1], 16, %2;"
                 :: "r"(saddr), "l"(g), "r"(sz) : "memory");
}
#define CP_COMMIT() asm volatile("cp.async.commit_group;" ::: "memory")
#define CP_WAIT(n)  asm volatile("cp.async.wait_group %0;" :: "n"(n) : "memory")

__device__ __forceinline__ void ldsm_x4(uint32_t& r0, uint32_t& r1, uint32_t& r2,
                                        uint32_t& r3, uint32_t a) {
    asm volatile("ldmatrix.sync.aligned.m8n8.x4.shared.b16 {%0,%1,%2,%3}, [%4];"
                 : "=r"(r0), "=r"(r1), "=r"(r2), "=r"(r3) : "r"(a));
}
__device__ __forceinline__ void ldsm_x2(uint32_t& r0, uint32_t& r1, uint32_t a) {
    asm volatile("ldmatrix.sync.aligned.m8n8.x2.shared.b16 {%0,%1}, [%2];"
                 : "=r"(r0), "=r"(r1) : "r"(a));
}
__device__ __forceinline__ void cvt_tf32(uint32_t& x) {
    asm("cvt.rna.tf32.f32 %0, %0;" : "+r"(x));
}
__device__ __forceinline__ void mma_tf32(float* c, const uint32_t* a, const uint32_t* b) {
    asm volatile("mma.sync.aligned.m16n8k8.row.col.f32.tf32.tf32.f32 "
                 "{%0,%1,%2,%3}, {%4,%5,%6,%7}, {%8,%9}, {%0,%1,%2,%3};"
                 : "+f"(c[0]), "+f"(c[1]), "+f"(c[2]), "+f"(c[3])
                 : "r"(a[0]), "r"(a[1]), "r"(a[2]), "r"(a[3]), "r"(b[0]), "r"(b[1]));
}

// ---------------- edge dtype detection + init (merged) ----------------
__global__ void k_detect_init(const unsigned int* __restrict__ ei32) {
    const int gtid = blockIdx.x * blockDim.x + threadIdx.x;
    if (blockIdx.x == 0) {
        unsigned v = ei32[2 * threadIdx.x + 1];
        if (threadIdx.x == 0) g_is64 = 1;
        __syncthreads();
        if (v) g_is64 = 0;
    }
    for (int i = gtid; i < NN; i += gridDim.x * blockDim.x) {
        g_deg[i] = 1;   // self loop
        g_cnt[i] = 1;
    }
}

__device__ __forceinline__ int load_edge(const void* __restrict__ ei, int idx) {
    if (g_is64) return (int)((const long long*)ei)[idx];
    return ((const int*)ei)[idx];
}

// ---------------- setup kernels ----------------
__global__ void k_count(const void* __restrict__ ei) {
    for (int e = blockIdx.x * blockDim.x + threadIdx.x; e < EE;
         e += gridDim.x * blockDim.x) {
        int s = load_edge(ei, e);
        int d = load_edge(ei, EE + e);
        if ((unsigned)s < NN && (unsigned)d < NN) {
            atomicAdd(&g_deg[s], 1);
            atomicAdd(&g_cnt[d], 1);
        }
    }
}

__global__ __launch_bounds__(1024) void k_scan_dis() {
    __shared__ int ssum[1024];
    const int t  = threadIdx.x;
    const int CH = (NN + 1023) / 1024;
    const int base = t * CH;

    int s = 0;
    for (int i = 0; i < CH; i++) {
        int idx = base + i;
        if (idx < NN) {
            s += g_cnt[idx];
            g_dis[idx] = rsqrtf((float)g_deg[idx]);
        }
    }
    ssum[t] = s;
    __syncthreads();
    for (int off = 1; off < 1024; off <<= 1) {
        int v = (t >= off) ? ssum[t - off] : 0;
        __syncthreads();
        ssum[t] += v;
        __syncthreads();
    }
    int run = (t == 0) ? 0 : ssum[t - 1];
    for (int i = 0; i < CH; i++) {
        int idx = base + i;
        if (idx < NN) {
            g_rowptr[idx] = run;
            g_cursor[idx] = run;
            run += g_cnt[idx];
        }
    }
    if (t == 1023) g_rowptr[NN] = ssum[1023];
}

__global__ void k_scatter(const void* __restrict__ ei) {
    for (int e = blockIdx.x * blockDim.x + threadIdx.x; e < ETOT;
         e += gridDim.x * blockDim.x) {
        int s, d;
        if (e < EE) {
            s = load_edge(ei, e);
            d = load_edge(ei, EE + e);
            if ((unsigned)s >= NN || (unsigned)d >= NN) continue;
        } else {
            s = d = e - EE;
        }
        int pos = atomicAdd(&g_cursor[d], 1);
        if ((unsigned)pos < ETOT) {
            g_srcv[pos] = s;
            g_wv[pos]   = g_dis[s] * g_dis[d];
        }
    }
}

// ---------------- tf32 mma GEMM (fp16 output rows) ----------------
// g_bufH[M,HPAD] = half(A[M,300] @ W[300,300]^T + bias); pad cols zeroed
#define SA_BYTES (128 * STRF * 4)
#define SB_BYTES (160 * STRF * 4)
#define SMEM_MMA (2 * SA_BYTES + 2 * SB_BYTES)   // 82944

__global__ void __launch_bounds__(256) k_gemm_tf32(const float* __restrict__ Aext,
                                                   const float* __restrict__ W,
                                                   const float* __restrict__ bias,
                                                   int src_flag) {
    extern __shared__ char smem[];
    const float* __restrict__ A = src_flag ? g_bufB : Aext;
    const uint32_t sb   = smem_u32(smem);
    const int tid  = threadIdx.x;
    const int wid  = tid >> 5;
    const int lane = tid & 31;
    const int wm   = wid & 1;
    const int wn   = wid >> 1;
    const int bm   = blockIdx.x * 128;
    const int bn   = blockIdx.y * 160;

    const uint32_t sA[2] = { sb,                sb + SA_BYTES };
    const uint32_t sB[2] = { sb + 2 * SA_BYTES, sb + 2 * SA_BYTES + SB_BYTES };

    float acc[4][5][4];
#pragma unroll
    for (int i = 0; i < 4; i++)
#pragma unroll
        for (int j = 0; j < 5; j++)
#pragma unroll
            for (int q = 0; q < 4; q++) acc[i][j][q] = 0.f;

    auto issue = [&](int c, int b) {
        const int k0 = c * KC;
#pragma unroll
        for (int t = 0; t < 4; t++) {
            int u   = tid + 256 * t;
            int row = u >> 3;
            int kc  = (u & 7) * 4;
            int gr  = bm + row;
            int gk  = k0 + kc;
            uint32_t sz = (gr < NN && gk < DD) ? 16u : 0u;
            if (gr >= NN) gr = NN - 1;
            if (gk >= DD) gk = 0;
            cp16(sA[b] + (row * STRF + kc) * 4, A + (size_t)gr * DD + gk, sz);
        }
#pragma unroll
        for (int t = 0; t < 5; t++) {
            int u   = tid + 256 * t;
            int row = u >> 3;
            int kc  = (u & 7) * 4;
            int gr  = bn + row;
            int gk  = k0 + kc;
            uint32_t sz = (gr < DD && gk < DD) ? 16u : 0u;
            if (gr >= DD) gr = 0;
            if (gk >= DD) gk = 0;
            cp16(sB[b] + (row * STRF + kc) * 4, W + (size_t)gr * DD + gk, sz);
        }
        CP_COMMIT();
    };

    issue(0, 0);
    issue(1, 1);

    for (int c = 0; c < NCH; c++) {
        if (c < NCH - 1) CP_WAIT(1); else CP_WAIT(0);
        __syncthreads();

        const int b = c & 1;
        const uint32_t a_base = sA[b];
        const uint32_t b_base = sB[b];

#pragma unroll
        for (int s = 0; s < 4; s++) {
            const int kb = s * 8;
            uint32_t af[4][4];
#pragma unroll
            for (int i = 0; i < 4; i++) {
                uint32_t addr = a_base +
                    ((wm * 64 + i * 16 + (lane & 15)) * STRF + kb + (lane >> 4) * 4) * 4;
                ldsm_x4(af[i][0], af[i][1], af[i][2], af[i][3], addr);
                cvt_tf32(af[i][0]); cvt_tf32(af[i][1]);
                cvt_tf32(af[i][2]); cvt_tf32(af[i][3]);
            }
            uint32_t bf[5][2];
#pragma unroll
            for (int j = 0; j < 5; j++) {
                uint32_t addr = b_base +
                    ((wn * 40 + j * 8 + (lane & 7)) * STRF + kb + ((lane >> 3) & 1) * 4) * 4;
                ldsm_x2(bf[j][0], bf[j][1], addr);
                cvt_tf32(bf[j][0]); cvt_tf32(bf[j][1]);
            }
#pragma unroll
            for (int i = 0; i < 4; i++)
#pragma unroll
                for (int j = 0; j < 5; j++)
                    mma_tf32(acc[i][j], af[i], bf[j]);
        }

        __syncthreads();
        if (c + 2 < NCH) issue(c + 2, b);
    }

    // ---- epilogue: bias + fp16 store into padded rows ----
    const int mrow = lane >> 2;
    const int ncol = 2 * (lane & 3);     // even
#pragma unroll
    for (int i = 0; i < 4; i++) {
#pragma unroll
        for (int j = 0; j < 5; j++) {
            int gc = bn + wn * 40 + j * 8 + ncol;
            if (gc >= HPAD) continue;
            __half2 hv0, hv1;
            if (gc < DD) {
                float bx = __ldg(bias + gc);
                float by = __ldg(bias + gc + 1);
                hv0 = __floats2half2_rn(acc[i][j][0] + bx, acc[i][j][1] + by);
                hv1 = __floats2half2_rn(acc[i][j][2] + bx, acc[i][j][3] + by);
            } else {
                hv0 = __floats2half2_rn(0.f, 0.f);
                hv1 = hv0;
            }
            int gr0 = bm + wm * 64 + i * 16 + mrow;
            if (gr0 < NN)
                *(__half2*)(g_bufH + (size_t)gr0 * HPAD + gc) = hv0;
            int gr1 = gr0 + 8;
            if (gr1 < NN)
                *(__half2*)(g_bufH + (size_t)gr1 * HPAD + gc) = hv1;
        }
    }
}

// ---------------- aggregation: warp/node, fp16 gather, fp32 accumulate ----------------
// fp16 row = 38 x 16B chunks. Lane covers chunk lane; lanes 0-5 also chunk 32+lane.
#define AGG_WPB 8

__device__ __forceinline__ void accum8(float* a, float w, const uint4& v) {
    const __half2* h = (const __half2*)&v;
#pragma unroll
    for (int i = 0; i < 4; i++) {
        float2 f = __half22float2(h[i]);
        a[2 * i]     += w * f.x;
        a[2 * i + 1] += w * f.y;
    }
}

__global__ __launch_bounds__(32 * AGG_WPB) void k_aggregate(float* __restrict__ Oext,
                                                            int dst_flag) {
    const int node = blockIdx.x * AGG_WPB + (threadIdx.x >> 5);
    if (node >= NN) return;
    const int lane = threadIdx.x & 31;
    const bool g1  = lane < 6;            // chunks 32..37
    const int  c0  = lane;
    const int  c1  = 32 + lane;

    const int beg = g_rowptr[node];
    const int end = g_rowptr[node + 1];

    float a0[8] = {0, 0, 0, 0, 0, 0, 0, 0};
    float a1[8] = {0, 0, 0, 0, 0, 0, 0, 0};

    int e = beg;
    for (; e + 2 <= end; e += 2) {
        const int   s0 = g_srcv[e],  s1 = g_srcv[e + 1];
        const float w0 = g_wv[e],    w1 = g_wv[e + 1];
        const uint4* p0 = (const uint4*)(g_bufH + (size_t)s0 * HPAD);
        const uint4* p1 = (const uint4*)(g_bufH + (size_t)s1 * HPAD);
        uint4 x0 = p0[c0], y0 = p1[c0];
        uint4 x1, y1;
        if (g1) { x1 = p0[c1]; y1 = p1[c1]; }
        accum8(a0, w0, x0);
        accum8(a0, w1, y0);
        if (g1) { accum8(a1, w0, x1); accum8(a1, w1, y1); }
    }
    if (e < end) {
        const int   s0 = g_srcv[e];
        const float w0 = g_wv[e];
        const uint4* p0 = (const uint4*)(g_bufH + (size_t)s0 * HPAD);
        accum8(a0, w0, p0[c0]);
        if (g1) accum8(a1, w0, p0[c1]);
    }

    float* orow;
    if (dst_flag) {
        orow = Oext + (size_t)node * DD;
    } else {
#pragma unroll
        for (int i = 0; i < 8; i++) {
            a0[i] = fmaxf(a0[i], 0.f);
            a1[i] = fmaxf(a1[i], 0.f);
        }
        orow = g_bufB + (size_t)node * DD;
    }
    // chunk c -> cols [8c, 8c+8): float4 idx 2c, 2c+1 (c=37: only first half valid)
    *(float4*)(orow + 8 * c0)     = make_float4(a0[0], a0[1], a0[2], a0[3]);
    *(float4*)(orow + 8 * c0 + 4) = make_float4(a0[4], a0[5], a0[6], a0[7]);
    if (g1) {
        *(float4*)(orow + 8 * c1) = make_float4(a1[0], a1[1], a1[2], a1[3]);
        if (c1 < 37)
            *(float4*)(orow + 8 * c1 + 4) = make_float4(a1[4], a1[5], a1[6], a1[7]);
    }
}

// ---------------- launch ----------------
extern "C" void kernel_launch(void* const* d_in, const int* in_sizes, int n_in,
                              void* d_out, int out_size) {
    const float* x   = (const float*)d_in[0];
    const void*  ei  = d_in[1];
    const float* W1  = (const float*)d_in[2];
    const float* b1  = (const float*)d_in[3];
    const float* W2  = (const float*)d_in[4];
    const float* b2  = (const float*)d_in[5];
    float*       out = (float*)d_out;

    static int smem_set = 0;
    if (!smem_set) {
        cudaFuncSetAttribute(k_gemm_tf32, cudaFuncAttributeMaxDynamicSharedMemorySize,
                             SMEM_MMA);
        smem_set = 1;
    }

    // graph setup
    k_detect_init<<<392, 256>>>((const unsigned int*)ei);
    k_count<<<1024, 256>>>(ei);
    k_scan_dis<<<1, 1024>>>();
    k_scatter<<<1024, 256>>>(ei);

    dim3 ggrid((NN + 127) / 128, 2);                 // 782 x 2
    const int agrid = (NN + AGG_WPB - 1) / AGG_WPB;  // 12500

    // layer 1: bufH = half(x @ W1^T + b1) ; bufB = relu(agg(bufH))
    k_gemm_tf32<<<ggrid, 256, SMEM_MMA>>>(x, W1, b1, 0);
    k_aggregate<<<agrid, 32 * AGG_WPB>>>(out, 0);

    // layer 2: bufH = half(bufB @ W2^T + b2) ; out = agg(bufH)
    k_gemm_tf32<<<ggrid, 256, SMEM_MMA>>>(nullptr, W2, b2, 1);
    k_aggregate<<<agrid, 32 * AGG_WPB>>>(out, 1);
}

// round 12
// speedup vs baseline: 1.2874x; 1.1761x over previous
#include <cuda_runtime.h>
#include <cuda_fp16.h>
#include <cstdint>

#define NN 100000
#define EE 800000
#define DD 300
#define ETOT (EE + NN)

// fp16 GEMM config: K padded to 320 halves, chunks of 64
#define KPH  320            // input row length in halves (640 B)
#define KC   64
#define NCH  (KPH / KC)     // 5
#define STR  72             // smem row stride in halves (144 B)
#define HPAD 304            // gather row length in halves (608 B, 38 x 16B)

// ---------------- scratch (static device memory; no allocation) ----------------
__device__ int   g_is64;
__device__ int   g_deg[NN];
__device__ int   g_cnt[NN];
__device__ int   g_cursor[NN];
__device__ int   g_rowptr[NN + 1];
__device__ float g_dis[NN];
__device__ int   g_srcv[ETOT];
__device__ float g_wv[ETOT];
__device__ __align__(16) __half g_inH[(size_t)NN * KPH];    // GEMM input (fp16, 64MB)
__device__ __align__(16) __half g_bufH[(size_t)NN * HPAD];  // GEMM output (fp16, 60.8MB)
__device__ __align__(16) __half g_Wh[KPH * KPH];            // fp16 weights (320x320)

// ---------------- PTX helpers (baseline sm_80-era ISA only) ----------------
__device__ __forceinline__ uint32_t smem_u32(const void* p) {
    uint32_t a;
    asm("{ .reg .u64 t; cvta.to.shared.u64 t, %1; cvt.u32.u64 %0, t; }" : "=r"(a) : "l"(p));
    return a;
}
__device__ __forceinline__ void cp16(uint32_t saddr, const void* g, uint32_t sz) {
    asm volatile("cp.async.cg.shared.global [%0], [%1], 16, %2;"
                 :: "r"(saddr), "l"(g), "r"(sz) : "memory");
}
#define CP_COMMIT() asm volatile("cp.async.commit_group;" ::: "memory")
#define CP_WAIT(n)  asm volatile("cp.async.wait_group %0;" :: "n"(n) : "memory")

__device__ __forceinline__ void ldsm_x4(uint32_t& r0, uint32_t& r1, uint32_t& r2,
                                        uint32_t& r3, uint32_t a) {
    asm volatile("ldmatrix.sync.aligned.m8n8.x4.shared.b16 {%0,%1,%2,%3}, [%4];"
                 : "=r"(r0), "=r"(r1), "=r"(r2), "=r"(r3) : "r"(a));
}
__device__ __forceinline__ void ldsm_x2(uint32_t& r0, uint32_t& r1, uint32_t a) {
    asm volatile("ldmatrix.sync.aligned.m8n8.x2.shared.b16 {%0,%1}, [%2];"
                 : "=r"(r0), "=r"(r1) : "r"(a));
}
__device__ __forceinline__ void mma16816(float* c, const uint32_t* a, const uint32_t* b) {
    asm volatile("mma.sync.aligned.m16n8k16.row.col.f32.f16.f16.f32 "
                 "{%0,%1,%2,%3}, {%4,%5,%6,%7}, {%8,%9}, {%0,%1,%2,%3};"
                 : "+f"(c[0]), "+f"(c[1]), "+f"(c[2]), "+f"(c[3])
                 : "r"(a[0]), "r"(a[1]), "r"(a[2]), "r"(a[3]), "r"(b[0]), "r"(b[1]));
}

// ---------------- edge dtype detection + init (merged) ----------------
__global__ void k_detect_init(const unsigned int* __restrict__ ei32) {
    const int gtid = blockIdx.x * blockDim.x + threadIdx.x;
    if (blockIdx.x == 0) {
        unsigned v = ei32[2 * threadIdx.x + 1];
        if (threadIdx.x == 0) g_is64 = 1;
        __syncthreads();
        if (v) g_is64 = 0;
    }
    for (int i = gtid; i < NN; i += gridDim.x * blockDim.x) {
        g_deg[i] = 1;   // self loop
        g_cnt[i] = 1;
    }
}

__device__ __forceinline__ int load_edge(const void* __restrict__ ei, int idx) {
    if (g_is64) return (int)((const long long*)ei)[idx];
    return ((const int*)ei)[idx];
}

// ---------------- setup kernels ----------------
__global__ void k_count(const void* __restrict__ ei) {
    for (int e = blockIdx.x * blockDim.x + threadIdx.x; e < EE;
         e += gridDim.x * blockDim.x) {
        int s = load_edge(ei, e);
        int d = load_edge(ei, EE + e);
        if ((unsigned)s < NN && (unsigned)d < NN) {
            atomicAdd(&g_deg[s], 1);
            atomicAdd(&g_cnt[d], 1);
        }
    }
}

__global__ __launch_bounds__(1024) void k_scan_dis() {
    __shared__ int ssum[1024];
    const int t  = threadIdx.x;
    const int CH = (NN + 1023) / 1024;
    const int base = t * CH;

    int s = 0;
    for (int i = 0; i < CH; i++) {
        int idx = base + i;
        if (idx < NN) {
            s += g_cnt[idx];
            g_dis[idx] = rsqrtf((float)g_deg[idx]);
        }
    }
    ssum[t] = s;
    __syncthreads();
    for (int off = 1; off < 1024; off <<= 1) {
        int v = (t >= off) ? ssum[t - off] : 0;
        __syncthreads();
        ssum[t] += v;
        __syncthreads();
    }
    int run = (t == 0) ? 0 : ssum[t - 1];
    for (int i = 0; i < CH; i++) {
        int idx = base + i;
        if (idx < NN) {
            g_rowptr[idx] = run;
            g_cursor[idx] = run;
            run += g_cnt[idx];
        }
    }
    if (t == 1023) g_rowptr[NN] = ssum[1023];
}

__global__ void k_scatter(const void* __restrict__ ei) {
    for (int e = blockIdx.x * blockDim.x + threadIdx.x; e < ETOT;
         e += gridDim.x * blockDim.x) {
        int s, d;
        if (e < EE) {
            s = load_edge(ei, e);
            d = load_edge(ei, EE + e);
            if ((unsigned)s >= NN || (unsigned)d >= NN) continue;
        } else {
            s = d = e - EE;
        }
        int pos = atomicAdd(&g_cursor[d], 1);
        if ((unsigned)pos < ETOT) {
            g_srcv[pos] = s;
            g_wv[pos]   = g_dis[s] * g_dis[d];
        }
    }
}

// ---------------- conversions ----------------
__global__ void k_xtoh(const float* __restrict__ x) {
    const size_t total = (size_t)NN * KPH;
    for (size_t i = (size_t)blockIdx.x * blockDim.x + threadIdx.x; i < total;
         i += (size_t)gridDim.x * blockDim.x) {
        int c = (int)(i % KPH);
        int r = (int)(i / KPH);
        g_inH[i] = (c < DD) ? __float2half_rn(x[(size_t)r * DD + c])
                            : __float2half_rn(0.f);
    }
}

__global__ void k_wtoh(const float* __restrict__ W) {
    for (int i = blockIdx.x * blockDim.x + threadIdx.x; i < KPH * KPH;
         i += gridDim.x * blockDim.x) {
        int r = i / KPH, c = i % KPH;
        g_Wh[i] = (r < DD && c < DD) ? __float2half_rn(W[(size_t)r * DD + c])
                                     : __float2half_rn(0.f);
    }
}

// ---------------- fp16 mma GEMM ----------------
// g_bufH[M,HPAD] = half(g_inH[M,:300] @ W^T + bias), fp32 accumulate.
// CTA 128x160, 8 warps (2 M x 4 N), warp tile 64x40; K in 5 chunks of 64 halves.
#define SA_BYTES (128 * STR * 2)     // 18432
#define SB_BYTES (160 * STR * 2)     // 23040
#define SMEM_MMA (2 * SA_BYTES + 2 * SB_BYTES)   // 82944

__global__ void __launch_bounds__(256) k_gemm_h(const float* __restrict__ bias) {
    extern __shared__ char smem[];
    const uint32_t sb   = smem_u32(smem);
    const int tid  = threadIdx.x;
    const int wid  = tid >> 5;
    const int lane = tid & 31;
    const int wm   = wid & 1;
    const int wn   = wid >> 1;
    const int bm   = blockIdx.x * 128;
    const int bn   = blockIdx.y * 160;

    const uint32_t sA[2] = { sb,                sb + SA_BYTES };
    const uint32_t sB[2] = { sb + 2 * SA_BYTES, sb + 2 * SA_BYTES + SB_BYTES };

    float acc[4][5][4];
#pragma unroll
    for (int i = 0; i < 4; i++)
#pragma unroll
        for (int j = 0; j < 5; j++)
#pragma unroll
            for (int q = 0; q < 4; q++) acc[i][j][q] = 0.f;

    auto issue = [&](int c, int b) {
        const int k0 = c * KC;
        // A: 128 rows x 64 halves = 1024 x 16B (4 per thread)
#pragma unroll
        for (int t = 0; t < 4; t++) {
            int u   = tid + 256 * t;
            int row = u >> 3;
            int kc  = (u & 7) * 8;
            int gr  = bm + row;
            uint32_t sz = (gr < NN) ? 16u : 0u;
            if (gr >= NN) gr = NN - 1;
            cp16(sA[b] + (row * STR + kc) * 2, g_inH + (size_t)gr * KPH + k0 + kc, sz);
        }
        // B: 160 rows x 64 halves = 1280 x 16B (5 per thread)
#pragma unroll
        for (int t = 0; t < 5; t++) {
            int u   = tid + 256 * t;
            int row = u >> 3;
            int kc  = (u & 7) * 8;
            cp16(sB[b] + (row * STR + kc) * 2,
                 g_Wh + (size_t)(bn + row) * KPH + k0 + kc, 16u);
        }
        CP_COMMIT();
    };

    issue(0, 0);
    issue(1, 1);

    for (int c = 0; c < NCH; c++) {
        if (c < NCH - 1) CP_WAIT(1); else CP_WAIT(0);
        __syncthreads();

        const int b = c & 1;
        const uint32_t a_base = sA[b];
        const uint32_t b_base = sB[b];

#pragma unroll
        for (int s = 0; s < 4; s++) {
            const int kb = s * 16;
            uint32_t af[4][4];
#pragma unroll
            for (int i = 0; i < 4; i++) {
                uint32_t addr = a_base +
                    ((wm * 64 + i * 16 + (lane & 15)) * STR + kb + (lane >> 4) * 8) * 2;
                ldsm_x4(af[i][0], af[i][1], af[i][2], af[i][3], addr);
            }
            uint32_t bf[5][2];
#pragma unroll
            for (int j = 0; j < 5; j++) {
                uint32_t addr = b_base +
                    ((wn * 40 + j * 8 + (lane & 7)) * STR + kb + ((lane >> 3) & 1) * 8) * 2;
                ldsm_x2(bf[j][0], bf[j][1], addr);
            }
#pragma unroll
            for (int i = 0; i < 4; i++)
#pragma unroll
                for (int j = 0; j < 5; j++)
                    mma16816(acc[i][j], af[i], bf[j]);
        }

        __syncthreads();
        if (c + 2 < NCH) issue(c + 2, b);
    }

    // ---- epilogue: bias + fp16 store into padded rows ----
    const int mrow = lane >> 2;
    const int ncol = 2 * (lane & 3);
#pragma unroll
    for (int i = 0; i < 4; i++) {
#pragma unroll
        for (int j = 0; j < 5; j++) {
            int gc = bn + wn * 40 + j * 8 + ncol;
            if (gc >= HPAD) continue;
            __half2 hv0, hv1;
            if (gc < DD) {
                float bx = __ldg(bias + gc);
                float by = __ldg(bias + gc + 1);
                hv0 = __floats2half2_rn(acc[i][j][0] + bx, acc[i][j][1] + by);
                hv1 = __floats2half2_rn(acc[i][j][2] + bx, acc[i][j][3] + by);
            } else {
                hv0 = __floats2half2_rn(0.f, 0.f);
                hv1 = hv0;
            }
            int gr0 = bm + wm * 64 + i * 16 + mrow;
            if (gr0 < NN)
                *(__half2*)(g_bufH + (size_t)gr0 * HPAD + gc) = hv0;
            int gr1 = gr0 + 8;
            if (gr1 < NN)
                *(__half2*)(g_bufH + (size_t)gr1 * HPAD + gc) = hv1;
        }
    }
}

// ---------------- aggregation: warp/node, fp16 gather, fp32 accumulate ----------------
// dst_flag 0: relu + fp16 store into g_inH (layer-2 GEMM input)
// dst_flag 1: fp32 store into Oext
#define AGG_WPB 8

__device__ __forceinline__ void accum8(float* a, float w, const uint4& v) {
    const __half2* h = (const __half2*)&v;
#pragma unroll
    for (int i = 0; i < 4; i++) {
        float2 f = __half22float2(h[i]);
        a[2 * i]     += w * f.x;
        a[2 * i + 1] += w * f.y;
    }
}

__global__ __launch_bounds__(32 * AGG_WPB) void k_aggregate(float* __restrict__ Oext,
                                                            int dst_flag) {
    const int node = blockIdx.x * AGG_WPB + (threadIdx.x >> 5);
    if (node >= NN) return;
    const int lane = threadIdx.x & 31;
    const bool g1  = lane < 6;            // chunks 32..37
    const int  c0  = lane;
    const int  c1  = 32 + lane;

    const int beg = g_rowptr[node];
    const int end = g_rowptr[node + 1];

    float a0[8] = {0, 0, 0, 0, 0, 0, 0, 0};
    float a1[8] = {0, 0, 0, 0, 0, 0, 0, 0};

    int e = beg;
    for (; e + 2 <= end; e += 2) {
        const int   s0 = g_srcv[e],  s1 = g_srcv[e + 1];
        const float w0 = g_wv[e],    w1 = g_wv[e + 1];
        const uint4* p0 = (const uint4*)(g_bufH + (size_t)s0 * HPAD);
        const uint4* p1 = (const uint4*)(g_bufH + (size_t)s1 * HPAD);
        uint4 x0 = p0[c0], y0 = p1[c0];
        uint4 x1, y1;
        if (g1) { x1 = p0[c1]; y1 = p1[c1]; }
        accum8(a0, w0, x0);
        accum8(a0, w1, y0);
        if (g1) { accum8(a1, w0, x1); accum8(a1, w1, y1); }
    }
    if (e < end) {
        const int   s0 = g_srcv[e];
        const float w0 = g_wv[e];
        const uint4* p0 = (const uint4*)(g_bufH + (size_t)s0 * HPAD);
        accum8(a0, w0, p0[c0]);
        if (g1) accum8(a1, w0, p0[c1]);
    }

    if (dst_flag) {
        float* orow = Oext + (size_t)node * DD;
        *(float4*)(orow + 8 * c0)     = make_float4(a0[0], a0[1], a0[2], a0[3]);
        *(float4*)(orow + 8 * c0 + 4) = make_float4(a0[4], a0[5], a0[6], a0[7]);
        if (g1) {
            *(float4*)(orow + 8 * c1) = make_float4(a1[0], a1[1], a1[2], a1[3]);
            if (c1 < 37)
                *(float4*)(orow + 8 * c1 + 4) = make_float4(a1[4], a1[5], a1[6], a1[7]);
        }
    } else {
        __half2 h0[4], h1[4];
#pragma unroll
        for (int i = 0; i < 4; i++) {
            h0[i] = __floats2half2_rn(fmaxf(a0[2 * i], 0.f), fmaxf(a0[2 * i + 1], 0.f));
            h1[i] = __floats2half2_rn(fmaxf(a1[2 * i], 0.f), fmaxf(a1[2 * i + 1], 0.f));
        }
        __half* orow = g_inH + (size_t)node * KPH;
        *(uint4*)(orow + 8 * c0) = *(const uint4*)h0;
        if (g1) *(uint4*)(orow + 8 * c1) = *(const uint4*)h1;
        // cols 304..319 of g_inH stay zero (written once by k_xtoh, zeros since
        // the gathered pad cols of g_bufH are zero -> here they're never touched)
    }
}

// ---------------- launch ----------------
extern "C" void kernel_launch(void* const* d_in, const int* in_sizes, int n_in,
                              void* d_out, int out_size) {
    const float* x   = (const float*)d_in[0];
    const void*  ei  = d_in[1];
    const float* W1  = (const float*)d_in[2];
    const float* b1  = (const float*)d_in[3];
    const float* W2  = (const float*)d_in[4];
    const float* b2  = (const float*)d_in[5];
    float*       out = (float*)d_out;

    static int smem_set = 0;
    if (!smem_set) {
        cudaFuncSetAttribute(k_gemm_h, cudaFuncAttributeMaxDynamicSharedMemorySize,
                             SMEM_MMA);
        smem_set = 1;
    }

    // graph setup
    k_detect_init<<<392, 256>>>((const unsigned int*)ei);
    k_count<<<1024, 256>>>(ei);
    k_scan_dis<<<1, 1024>>>();
    k_scatter<<<1024, 256>>>(ei);

    dim3 ggrid((NN + 127) / 128, 2);                 // 782 x 2
    const int agrid = (NN + AGG_WPB - 1) / AGG_WPB;  // 12500

    // layer 1
    k_xtoh<<<4096, 256>>>(x);
    k_wtoh<<<100, 256>>>(W1);
    k_gemm_h<<<ggrid, 256, SMEM_MMA>>>(b1);
    k_aggregate<<<agrid, 32 * AGG_WPB>>>(out, 0);

    // layer 2
    k_wtoh<<<100, 256>>>(W2);
    k_gemm_h<<<ggrid, 256, SMEM_MMA>>>(b2);
    k_aggregate<<<agrid, 32 * AGG_WPB>>>(out, 1);
}